// round 5
// baseline (speedup 1.0000x reference)
#include <cuda_runtime.h>
#include <cstdint>

#define Bdim 2
#define Hdim 16
#define Sdim 2048
#define Ddim 128
#define QT 128           // q-tile rows per CTA
#define KT 64            // kv-tile rows (double buffered)
#define NT (Sdim / KT)   // 32 kv tiles
#define NTHREADS 512

// smem strides (floats): bank-conflict-free fragment access (verified)
#define QSTRIDE 136
#define KSTRIDE 136
#define VSTRIDE 132

#define QS_OFF 0
#define KS_OFF (QT * QSTRIDE)                       // Q: 128 rows
#define VS_OFF (KS_OFF + 2 * KT * KSTRIDE)         // K: 2 x 64 rows
#define SMEM_WORDS (VS_OFF + 2 * KT * VSTRIDE)     // V: 2 x 64 rows
#define SMEM_BYTES (SMEM_WORDS * 4)                // 206848 B -> 1 CTA/SM

#define SHIFT1 1.00048828125f   // 1 + 2^-11 : Q-side truncation-bias compensation
#define SHIFTH 1.00024411f      // sqrt(1 + 2^-11) : P-side (applied before square)

// ---------------------------------------------------------------------------
static __device__ __forceinline__ uint32_t cvt_tf32(float f) {
    uint32_t r;
    asm("cvt.rna.tf32.f32 %0, %1;" : "=r"(r) : "f"(f));
    return r;
}

static __device__ __forceinline__ void mma8(float* d,
        uint32_t a0, uint32_t a1, uint32_t a2, uint32_t a3,
        uint32_t b0, uint32_t b1) {
    asm volatile(
        "mma.sync.aligned.m16n8k8.row.col.f32.tf32.tf32.f32 "
        "{%0,%1,%2,%3}, {%4,%5,%6,%7}, {%8,%9}, {%0,%1,%2,%3};"
        : "+f"(d[0]), "+f"(d[1]), "+f"(d[2]), "+f"(d[3])
        : "r"(a0), "r"(a1), "r"(a2), "r"(a3), "r"(b0), "r"(b1));
}

static __device__ __forceinline__ void cp16(const float* smem_dst, const float* gsrc) {
    unsigned sa = (unsigned)__cvta_generic_to_shared(smem_dst);
    asm volatile("cp.async.cg.shared.global [%0], [%1], 16;" :: "r"(sa), "l"(gsrc));
}
#define CP_COMMIT() asm volatile("cp.async.commit_group;" ::: "memory")
#define CP_WAIT(n)  asm volatile("cp.async.wait_group %0;" :: "n"(n) : "memory")

// Issue cp.async for a full 64-row K+V tile into buffer `buf`. All 512 threads.
static __device__ __forceinline__ void issue_tile(
        float* sm, const float* __restrict__ kb, const float* __restrict__ vb,
        int buf, int tile, int tid) {
    const float* kg = kb + (size_t)tile * KT * Ddim;
    const float* vg = vb + (size_t)tile * KT * Ddim;
    float* kd = sm + KS_OFF + buf * KT * KSTRIDE;
    float* vd = sm + VS_OFF + buf * KT * VSTRIDE;
    #pragma unroll
    for (int i = 0; i < 4; i++) {
        int c = tid + NTHREADS * i;        // 0..2047
        int r = c >> 5, col = (c & 31) << 2;
        cp16(kd + r * KSTRIDE + col, kg + r * Ddim + col);
    }
    #pragma unroll
    for (int i = 0; i < 4; i++) {
        int c = tid + NTHREADS * i;
        int r = c >> 5, col = (c & 31) << 2;
        cp16(vd + r * VSTRIDE + col, vg + r * Ddim + col);
    }
}

// ---------------------------------------------------------------------------
// One CTA (512 thr, 16 warps) = one (b,h) x one 128-row q-tile.
// wm = wid&7 (m16 block), wn = wid>>3 (kv32 half of the 64-row kv tile).
// Per phase (one kv tile): S(m16 x kv32, 4 chains) -> P in regs (C->A reuse)
// -> O(m16 x d128, 16 chains) += P @ V. KV double-buffered: tile t+1 streams
// via cp.async during compute of tile t. One __syncthreads per phase.
// O reduced across the two wn halves at the end.
// ---------------------------------------------------------------------------
__global__ void __launch_bounds__(NTHREADS, 1)
attn_relu2_kernel(const float* __restrict__ q, const float* __restrict__ k,
                  const float* __restrict__ v, const float* __restrict__ scale_p,
                  float* __restrict__ out) {
    extern __shared__ float sm[];
    float* QS = sm + QS_OFF;

    const int tid  = threadIdx.x;
    const int lane = tid & 31;
    const int g    = lane >> 2;    // 0..7
    const int t4   = lane & 3;     // 0..3
    const int wid  = tid >> 5;
    const int wm   = wid & 7;      // m16 block (0..7)
    const int wn   = wid >> 3;     // kv-half (0..1)

    const int bh = blockIdx.x >> 4;           // 0..31
    const int q0 = (blockIdx.x & 15) << 7;    // q-tile base (128 rows)

    const float* kbase = k + (size_t)bh * Sdim * Ddim;
    const float* vbase = v + (size_t)bh * Sdim * Ddim;

    // ---- prologue: stream tile 0 into buf 0; fill Q (scale folded, tf32) ----
    issue_tile(sm, kbase, vbase, 0, 0, tid); CP_COMMIT();

    {
        const float scl2 = (*scale_p) * SHIFT1;
        const float* qg = q + ((size_t)bh * Sdim + q0) * Ddim;
        #pragma unroll
        for (int i = 0; i < 8; i++) {
            int c = tid + NTHREADS * i;    // 0..4095
            int r = c >> 5, col = (c & 31) << 2;
            float4 f = *reinterpret_cast<const float4*>(qg + r * Ddim + col);
            uint4 u;
            u.x = cvt_tf32(f.x * scl2); u.y = cvt_tf32(f.y * scl2);
            u.z = cvt_tf32(f.z * scl2); u.w = cvt_tf32(f.w * scl2);
            *reinterpret_cast<uint4*>(QS + r * QSTRIDE + col) = u;
        }
    }

    float O[16][4];
    #pragma unroll
    for (int nd = 0; nd < 16; nd++)
        #pragma unroll
        for (int i = 0; i < 4; i++) O[nd][i] = 0.0f;

    const float* qrow0 = QS + (wm * 16 + g) * QSTRIDE + 2 * t4;

    // ---- main loop: one phase per kv tile ----
    #pragma unroll 1
    for (int tt = 0; tt < NT; tt++) {
        __syncthreads();   // all warps done computing on buf (tt+1)&1's old data
        if (tt + 1 < NT) {
            issue_tile(sm, kbase, vbase, (tt + 1) & 1, tt + 1, tid);
            CP_COMMIT();
            CP_WAIT(1);    // tile tt resident (its loads overlapped phase tt-1)
        } else {
            CP_WAIT(0);
        }

        const float* Kb = sm + KS_OFF + (tt & 1) * KT * KSTRIDE;
        const float* Vb = sm + VS_OFF + (tt & 1) * KT * VSTRIDE;

        // ---- GEMM1: S(m16 x kv32) = Qs @ K^T over d (16 k-steps, 4 chains) ----
        float S[4][4];
        #pragma unroll
        for (int nb = 0; nb < 4; nb++)
            #pragma unroll
            for (int i = 0; i < 4; i++) S[nb][i] = 0.0f;

        const float* krow0 = Kb + (wn * 32 + g) * KSTRIDE + 2 * t4;
        #pragma unroll 4
        for (int ks = 0; ks < 16; ks++) {
            uint2 A0 = *reinterpret_cast<const uint2*>(qrow0 + 8 * ks);
            uint2 A1 = *reinterpret_cast<const uint2*>(qrow0 + 8 * QSTRIDE + 8 * ks);
            #pragma unroll
            for (int nb = 0; nb < 4; nb++) {
                float2 b = *reinterpret_cast<const float2*>(
                    krow0 + nb * 8 * KSTRIDE + 8 * ks);
                mma8(S[nb], A0.x, A1.x, A0.y, A1.y,
                     __float_as_uint(b.x), __float_as_uint(b.y));
            }
        }

        // ---- P = tf32(relu(S)^2 * shift); GEMM2: O += P @ V (16 chains) ----
        #pragma unroll
        for (int s2 = 0; s2 < 4; s2++) {
            uint32_t pA[4];
            #pragma unroll
            for (int i = 0; i < 4; i++) {
                float f = fmaxf(S[s2][i], 0.0f) * SHIFTH;
                pA[i] = cvt_tf32(f * f);
            }
            const float* vrow = Vb + (wn * 32 + s2 * 8 + 2 * t4) * VSTRIDE + g;
            #pragma unroll 8
            for (int nd = 0; nd < 16; nd++) {
                uint32_t b0 = __float_as_uint(vrow[nd * 8]);
                uint32_t b1 = __float_as_uint(vrow[nd * 8 + VSTRIDE]);
                // A-frag = (c0, c2, c1, c3) of the S block (k-order permute)
                mma8(O[nd], pA[0], pA[2], pA[1], pA[3], b0, b1);
            }
        }
    }

    // ---- reduce O across the two kv-halves, write out ----
    __syncthreads();
    float* red = sm + KS_OFF;   // reuse K buffers: 128 x 136 region
    if (wn == 1) {
        int r0 = wm * 16 + g;
        #pragma unroll
        for (int nd = 0; nd < 16; nd++) {
            *reinterpret_cast<float2*>(red + r0 * 136 + nd * 8 + 2 * t4) =
                make_float2(O[nd][0], O[nd][1]);
            *reinterpret_cast<float2*>(red + (r0 + 8) * 136 + nd * 8 + 2 * t4) =
                make_float2(O[nd][2], O[nd][3]);
        }
    }
    __syncthreads();
    if (wn == 0) {
        float* ob = out + ((size_t)bh * Sdim + q0) * Ddim;
        int r0 = wm * 16 + g;
        #pragma unroll
        for (int nd = 0; nd < 16; nd++) {
            float2 ra = *reinterpret_cast<const float2*>(red + r0 * 136 + nd * 8 + 2 * t4);
            float2 rb = *reinterpret_cast<const float2*>(red + (r0 + 8) * 136 + nd * 8 + 2 * t4);
            *reinterpret_cast<float2*>(ob + r0 * Ddim + nd * 8 + 2 * t4) =
                make_float2(O[nd][0] + ra.x, O[nd][1] + ra.y);
            *reinterpret_cast<float2*>(ob + (r0 + 8) * Ddim + nd * 8 + 2 * t4) =
                make_float2(O[nd][2] + rb.x, O[nd][3] + rb.y);
        }
    }
}

extern "C" void kernel_launch(void* const* d_in, const int* in_sizes, int n_in,
                              void* d_out, int out_size) {
    (void)in_sizes; (void)n_in; (void)out_size;
    const float* q = (const float*)d_in[0];
    const float* k = (const float*)d_in[1];
    const float* v = (const float*)d_in[2];
    const float* scale = (const float*)d_in[3];
    float* out = (float*)d_out;

    cudaFuncSetAttribute(attn_relu2_kernel,
                         cudaFuncAttributeMaxDynamicSharedMemorySize, SMEM_BYTES);

    dim3 grid(Bdim * Hdim * (Sdim / QT));   // 512 CTAs, bh-major
    attn_relu2_kernel<<<grid, NTHREADS, SMEM_BYTES>>>(q, k, v, scale, out);
}

// round 6
// speedup vs baseline: 1.9261x; 1.9261x over previous
#include <cuda_runtime.h>
#include <cstdint>

#define Bdim 2
#define Hdim 16
#define Sdim 2048
#define Ddim 128
#define QT 64            // q-tile rows per CTA
#define KT 64            // kv-tile rows
#define NT (Sdim / KT)   // 32 kv tiles
#define NTHREADS 256

// K/V smem strides (floats): bank-conflict-free fragment access (verified)
#define KSTRIDE 136
#define VSTRIDE 132
// Q stored as fp16: 136 halves per row = 68 words
#define QWSTRIDE 68

#define QS_OFF 0                              // words
#define KS_OFF (QT * QWSTRIDE)                // Q: 64 rows x 68 words
#define VS_OFF (KS_OFF + KT * KSTRIDE)
#define SMEM_WORDS (VS_OFF + KT * VSTRIDE)
#define SMEM_BYTES (SMEM_WORDS * 4)           // 86016 B -> 2 CTAs/SM

// ---------------------------------------------------------------------------
// pack two f32 into f16x2 (lo = first arg). cvt.rn.f16x2.f32 d,a,b: a -> upper.
static __device__ __forceinline__ uint32_t h2(float lo, float hi) {
    uint32_t r;
    asm("cvt.rn.f16x2.f32 %0, %1, %2;" : "=r"(r) : "f"(hi), "f"(lo));
    return r;
}

static __device__ __forceinline__ void mma16(float* d,
        uint32_t a0, uint32_t a1, uint32_t a2, uint32_t a3,
        uint32_t b0, uint32_t b1) {
    asm volatile(
        "mma.sync.aligned.m16n8k16.row.col.f32.f16.f16.f32 "
        "{%0,%1,%2,%3}, {%4,%5,%6,%7}, {%8,%9}, {%0,%1,%2,%3};"
        : "+f"(d[0]), "+f"(d[1]), "+f"(d[2]), "+f"(d[3])
        : "r"(a0), "r"(a1), "r"(a2), "r"(a3), "r"(b0), "r"(b1));
}

static __device__ __forceinline__ void cp16(const float* smem_dst, const float* gsrc) {
    unsigned sa = (unsigned)__cvta_generic_to_shared(smem_dst);
    asm volatile("cp.async.cg.shared.global [%0], [%1], 16;" :: "r"(sa), "l"(gsrc));
}
#define CP_COMMIT() asm volatile("cp.async.commit_group;" ::: "memory")
#define CP_WAIT(n)  asm volatile("cp.async.wait_group %0;" :: "n"(n) : "memory")

static __device__ __forceinline__ void bar_sync(int id, int cnt) {
    asm volatile("bar.sync %0, %1;" :: "r"(id), "r"(cnt) : "memory");
}

// Issue cp.async for one kv-quarter (16 rows of K and V, fp32) of tile `tile`.
// Called by 128 threads of the kv-group that owns quarter qq; tid_h in [0,128).
static __device__ __forceinline__ void issue_quarter(
        float* sm, const float* __restrict__ kb, const float* __restrict__ vb,
        int qq, int tile, int tid_h) {
    const float* kg = kb + (size_t)(tile * KT + qq * 16) * Ddim;
    const float* vg = vb + (size_t)(tile * KT + qq * 16) * Ddim;
    #pragma unroll
    for (int i = 0; i < 4; i++) {
        int c = tid_h + 128 * i;          // 0..511
        int r = c >> 5, col = (c & 31) << 2;
        cp16(sm + KS_OFF + (qq * 16 + r) * KSTRIDE + col, kg + r * Ddim + col);
    }
    #pragma unroll
    for (int i = 0; i < 4; i++) {
        int c = tid_h + 128 * i;
        int r = c >> 5, col = (c & 31) << 2;
        cp16(sm + VS_OFF + (qq * 16 + r) * VSTRIDE + col, vg + r * Ddim + col);
    }
}

// ---------------------------------------------------------------------------
// One CTA = one (b,h) x one 64-row q-tile. 8 warps: wm = wid&3 (m16 block),
// wn = wid>>2 (kv-half group). Two CTAs/SM. Per phase (kv-quarter 16):
// S(m16 x kv16, fp16 mma k16) -> P packed to f16x2 in regs (C->A direct) ->
// O(m16 x d128) += P @ V (one k16 step, 16 chains). kv-halves decoupled on
// named barriers with quarter-granular cp.async. O reduced across halves.
// ---------------------------------------------------------------------------
__global__ void __launch_bounds__(NTHREADS, 2)
attn_relu2_kernel(const float* __restrict__ q, const float* __restrict__ k,
                  const float* __restrict__ v, const float* __restrict__ scale_p,
                  float* __restrict__ out) {
    extern __shared__ float sm[];
    uint32_t* QW = reinterpret_cast<uint32_t*>(sm);   // Q as f16x2 words
    float* KS = sm + KS_OFF;
    float* VS = sm + VS_OFF;

    const int tid  = threadIdx.x;
    const int lane = tid & 31;
    const int g    = lane >> 2;    // 0..7
    const int t4   = lane & 3;     // 0..3
    const int wid  = tid >> 5;
    const int wm   = wid & 3;      // m16 block
    const int wn   = wid >> 2;     // kv-half group
    const int tid_h = tid & 127;

    const int bh = blockIdx.x >> 5;           // 0..31
    const int q0 = (blockIdx.x & 31) << 6;    // q-tile base (64 rows)

    const float* kbase = k + (size_t)bh * Sdim * Ddim;
    const float* vbase = v + (size_t)bh * Sdim * Ddim;

    // ---- prologue: stream tile-0 quarters, fill Q (scale folded, fp16) ----
    issue_quarter(sm, kbase, vbase, wn * 2 + 0, 0, tid_h); CP_COMMIT();
    issue_quarter(sm, kbase, vbase, wn * 2 + 1, 0, tid_h); CP_COMMIT();

    {
        const float scl = *scale_p;
        const float* qg = q + ((size_t)bh * Sdim + q0) * Ddim;
        #pragma unroll
        for (int i = 0; i < 8; i++) {
            int c = tid + 256 * i;         // 0..2047 float4 chunks
            int r = c >> 5, c4 = (c & 31) << 2;     // col in floats
            float4 f = *reinterpret_cast<const float4*>(qg + r * Ddim + c4);
            uint2 u;
            u.x = h2(f.x * scl, f.y * scl);
            u.y = h2(f.z * scl, f.w * scl);
            *reinterpret_cast<uint2*>(QW + r * QWSTRIDE + (c4 >> 1)) = u;
        }
    }
    __syncthreads();

    float O[16][4];
    #pragma unroll
    for (int nd = 0; nd < 16; nd++)
        #pragma unroll
        for (int i = 0; i < 4; i++) O[nd][i] = 0.0f;

    const uint32_t* qw0 = QW + (wm * 16 + g) * QWSTRIDE + t4;

    // ---- main loop ----
    #pragma unroll 1
    for (int tt = 0; tt < NT; tt++) {
        const bool lastt = (tt == NT - 1);
        #pragma unroll
        for (int p = 0; p < 2; p++) {
            const int qq = wn * 2 + p;     // kv-quarter owned this phase

            if (lastt && p == 1) { CP_WAIT(0); } else { CP_WAIT(1); }
            bar_sync(1 + wn, 128);

            // ---- GEMM1: S(m16 x kv16) = Qh @ K^T over d (8 k16-steps) ----
            float S[2][4];
            #pragma unroll
            for (int nb = 0; nb < 2; nb++)
                #pragma unroll
                for (int i = 0; i < 4; i++) S[nb][i] = 0.0f;

            const float* krow0 = KS + (qq * 16 + g) * KSTRIDE + 2 * t4;
            #pragma unroll
            for (int kb = 0; kb < 8; kb++) {
                uint32_t a0 = qw0[8 * kb];
                uint32_t a1 = qw0[8 * QWSTRIDE + 8 * kb];
                uint32_t a2 = qw0[8 * kb + 4];
                uint32_t a3 = qw0[8 * QWSTRIDE + 8 * kb + 4];
                #pragma unroll
                for (int nb = 0; nb < 2; nb++) {
                    const float* kp = krow0 + nb * 8 * KSTRIDE + 16 * kb;
                    float2 x = *reinterpret_cast<const float2*>(kp);
                    float2 y = *reinterpret_cast<const float2*>(kp + 8);
                    mma16(S[nb], a0, a1, a2, a3, h2(x.x, x.y), h2(y.x, y.y));
                }
            }

            // ---- P = f16(relu(S)^2); GEMM2: O += P @ V (one k16 step) ----
            uint32_t pA[4];
            {
                float p00 = fmaxf(S[0][0], 0.0f), p01 = fmaxf(S[0][1], 0.0f);
                float p02 = fmaxf(S[0][2], 0.0f), p03 = fmaxf(S[0][3], 0.0f);
                float p10 = fmaxf(S[1][0], 0.0f), p11 = fmaxf(S[1][1], 0.0f);
                float p12 = fmaxf(S[1][2], 0.0f), p13 = fmaxf(S[1][3], 0.0f);
                pA[0] = h2(p00 * p00, p01 * p01);
                pA[1] = h2(p02 * p02, p03 * p03);
                pA[2] = h2(p10 * p10, p11 * p11);
                pA[3] = h2(p12 * p12, p13 * p13);
            }
            const float* v0 = VS + (qq * 16 + 2 * t4) * VSTRIDE + g;
            #pragma unroll 8
            for (int nd = 0; nd < 16; nd++) {
                const float* vp = v0 + nd * 8;
                uint32_t b0 = h2(vp[0],           vp[VSTRIDE]);
                uint32_t b1 = h2(vp[8 * VSTRIDE], vp[9 * VSTRIDE]);
                mma16(O[nd], pA[0], pA[1], pA[2], pA[3], b0, b1);
            }

            bar_sync(1 + wn, 128);
            if (!lastt) {
                issue_quarter(sm, kbase, vbase, qq, tt + 1, tid_h);
                CP_COMMIT();
            }
        }
    }

    // ---- reduce O across the two kv-halves, write out ----
    __syncthreads();
    float* red = KS;   // reuse K region: 64 x 136 floats
    if (wn == 1) {
        int r0 = wm * 16 + g;
        #pragma unroll
        for (int nd = 0; nd < 16; nd++) {
            *reinterpret_cast<float2*>(red + r0 * 136 + nd * 8 + 2 * t4) =
                make_float2(O[nd][0], O[nd][1]);
            *reinterpret_cast<float2*>(red + (r0 + 8) * 136 + nd * 8 + 2 * t4) =
                make_float2(O[nd][2], O[nd][3]);
        }
    }
    __syncthreads();
    if (wn == 0) {
        float* ob = out + ((size_t)bh * Sdim + q0) * Ddim;
        int r0 = wm * 16 + g;
        #pragma unroll
        for (int nd = 0; nd < 16; nd++) {
            float2 ra = *reinterpret_cast<const float2*>(red + r0 * 136 + nd * 8 + 2 * t4);
            float2 rb = *reinterpret_cast<const float2*>(red + (r0 + 8) * 136 + nd * 8 + 2 * t4);
            *reinterpret_cast<float2*>(ob + r0 * Ddim + nd * 8 + 2 * t4) =
                make_float2(O[nd][0] + ra.x, O[nd][1] + ra.y);
            *reinterpret_cast<float2*>(ob + (r0 + 8) * Ddim + nd * 8 + 2 * t4) =
                make_float2(O[nd][2] + rb.x, O[nd][3] + rb.y);
        }
    }
}

extern "C" void kernel_launch(void* const* d_in, const int* in_sizes, int n_in,
                              void* d_out, int out_size) {
    (void)in_sizes; (void)n_in; (void)out_size;
    const float* q = (const float*)d_in[0];
    const float* k = (const float*)d_in[1];
    const float* v = (const float*)d_in[2];
    const float* scale = (const float*)d_in[3];
    float* out = (float*)d_out;

    cudaFuncSetAttribute(attn_relu2_kernel,
                         cudaFuncAttributeMaxDynamicSharedMemorySize, SMEM_BYTES);

    dim3 grid(Bdim * Hdim * (Sdim / QT));   // 1024 CTAs, bh-major
    attn_relu2_kernel<<<grid, NTHREADS, SMEM_BYTES>>>(q, k, v, scale, out);
}

// round 7
// speedup vs baseline: 3.3585x; 1.7437x over previous
#include <cuda_runtime.h>
#include <cstdint>

#define Bdim 2
#define Hdim 16
#define Sdim 2048
#define Ddim 128
#define QT 64            // q-tile rows per CTA
#define PH_KV 64         // kv rows consumed per phase (32 per group)
#define NPH (Sdim / PH_KV)   // 32 phases
#define NTHREADS 256

// word strides (fp16 packed as uint32 words)
#define QWSTRIDE 68      // Q row: 64 words (128 halves) + 4 pad
#define KWSTRIDE 68      // K row: 64 words (128 halves) + 4 pad
#define VWSTRIDE 136     // V'' rpair row: 128 words (one per d) + 8 pad

#define QS_OFF 0
#define KS_OFF (QT * QWSTRIDE)                    // 4352
#define VS_OFF (KS_OFF + 128 * KWSTRIDE)          // K: 2grp x 2buf x 32 rows
#define SMEM_WORDS (VS_OFF + 64 * VWSTRIDE)       // V'': 2grp x 2buf x 16 rpairs
#define SMEM_BYTES (SMEM_WORDS * 4)               // 87040 B -> 2 CTAs/SM

// ---------------------------------------------------------------------------
// pack two f32 into f16x2 word: lo -> low half, hi -> high half.
static __device__ __forceinline__ uint32_t h2(float lo, float hi) {
    uint32_t r;
    asm("cvt.rn.f16x2.f32 %0, %1, %2;" : "=r"(r) : "f"(hi), "f"(lo));
    return r;
}

static __device__ __forceinline__ void mma16(float* d,
        uint32_t a0, uint32_t a1, uint32_t a2, uint32_t a3,
        uint32_t b0, uint32_t b1) {
    asm volatile(
        "mma.sync.aligned.m16n8k16.row.col.f32.f16.f16.f32 "
        "{%0,%1,%2,%3}, {%4,%5,%6,%7}, {%8,%9}, {%0,%1,%2,%3};"
        : "+f"(d[0]), "+f"(d[1]), "+f"(d[2]), "+f"(d[3])
        : "r"(a0), "r"(a1), "r"(a2), "r"(a3), "r"(b0), "r"(b1));
}

static __device__ __forceinline__ void bar_sync(int id, int cnt) {
    asm volatile("bar.sync %0, %1;" :: "r"(id), "r"(cnt) : "memory");
}

// ---------------------------------------------------------------------------
// One CTA = one (b,h) x one 64-row q-tile. 8 warps: wm = wid&3 (m16 block),
// wn = wid>>2 (kv-group). 2 CTAs/SM. Each phase: group wn consumes 32 kv rows
// from its double-buffered fp16 K/V smem, while next phase's 32 rows are
// LDG-staged -> cvt f16 -> STS into the spare buffer. One named bar per phase.
// GEMM1 S(m16 x kv32) fp16 mma; P = f16(relu(S)^2) packed in regs (C->A
// direct); GEMM2 O(m16 x d128) += P @ V'' (2 k16 steps). O reduced across
// the two groups at the end.
// ---------------------------------------------------------------------------
__global__ void __launch_bounds__(NTHREADS, 2)
attn_relu2_kernel(const float* __restrict__ q, const float* __restrict__ k,
                  const float* __restrict__ v, const float* __restrict__ scale_p,
                  float* __restrict__ out) {
    extern __shared__ uint32_t smw[];
    uint32_t* QW = smw + QS_OFF;
    uint32_t* KW = smw + KS_OFF;
    uint32_t* VW = smw + VS_OFF;

    const int tid  = threadIdx.x;
    const int lane = tid & 31;
    const int g    = lane >> 2;    // 0..7
    const int t4   = lane & 3;     // 0..3
    const int wid  = tid >> 5;
    const int wm   = wid & 3;      // m16 block
    const int wn   = wid >> 2;     // kv group
    const int tid_h = tid & 127;

    const int bh = blockIdx.x >> 5;           // 0..31
    const int q0 = (blockIdx.x & 31) << 6;    // q-tile base (64 rows)

    const float* kbase = k + (size_t)bh * Sdim * Ddim;
    const float* vbase = v + (size_t)bh * Sdim * Ddim;

    // per-thread load coords
    const int kr = tid_h >> 2, kq = tid_h & 3;     // K: row (0..31), col-q
    const int vrp = tid_h >> 3, vc = tid_h & 7;    // V: rpair (0..15), col-chunk

    // ---- Q fill (scale folded, fp16 packed) ----
    {
        const float scl = *scale_p;
        const float* qg = q + ((size_t)bh * Sdim + q0) * Ddim;
        #pragma unroll
        for (int i = 0; i < 8; i++) {
            int c = tid + 256 * i;
            int r = c >> 5, c4 = (c & 31) << 2;
            float4 f = *reinterpret_cast<const float4*>(qg + r * Ddim + c4);
            uint2 u;
            u.x = h2(f.x * scl, f.y * scl);
            u.y = h2(f.z * scl, f.w * scl);
            *reinterpret_cast<uint2*>(QW + r * QWSTRIDE + (c4 >> 1)) = u;
        }
    }

    // ---- prologue: load phase-0 K/V into buf 0 ----
    {
        const float* kg = kbase + (size_t)(wn * 32) * Ddim;
        const float* vg = vbase + (size_t)(wn * 32) * Ddim;
        uint32_t* kd = KW + (size_t)(wn * 2 + 0) * 32 * KWSTRIDE;
        uint32_t* vd = VW + (size_t)(wn * 2 + 0) * 16 * VWSTRIDE;
        #pragma unroll
        for (int i = 0; i < 8; i++) {
            float4 f = *reinterpret_cast<const float4*>(kg + kr * Ddim + 16 * i + 4 * kq);
            *reinterpret_cast<uint2*>(kd + kr * KWSTRIDE + 8 * i + 2 * kq) =
                make_uint2(h2(f.x, f.y), h2(f.z, f.w));
        }
        #pragma unroll
        for (int m = 0; m < 4; m++) {
            int d0 = 4 * vc + 32 * m;
            float4 a = *reinterpret_cast<const float4*>(vg + (2 * vrp) * Ddim + d0);
            float4 b = *reinterpret_cast<const float4*>(vg + (2 * vrp + 1) * Ddim + d0);
            *reinterpret_cast<uint4*>(vd + vrp * VWSTRIDE + d0) =
                make_uint4(h2(a.x, b.x), h2(a.y, b.y), h2(a.z, b.z), h2(a.w, b.w));
        }
    }
    __syncthreads();

    float O[16][4];
    #pragma unroll
    for (int nd = 0; nd < 16; nd++)
        #pragma unroll
        for (int i = 0; i < 4; i++) O[nd][i] = 0.0f;

    const uint32_t* qw0 = QW + (wm * 16 + g) * QWSTRIDE + t4;

    // ---- main loop: 32 phases ----
    #pragma unroll 1
    for (int t = 0; t < NPH; t++) {
        const int buf = t & 1;
        const bool more = (t + 1 < NPH);
        const uint32_t* Kb = KW + (size_t)(wn * 2 + buf) * 32 * KWSTRIDE;
        const uint32_t* Vb = VW + (size_t)(wn * 2 + buf) * 16 * VWSTRIDE;
        uint32_t* kd = KW + (size_t)(wn * 2 + (buf ^ 1)) * 32 * KWSTRIDE;
        uint32_t* vd = VW + (size_t)(wn * 2 + (buf ^ 1)) * 16 * VWSTRIDE;
        const float* kgn = kbase + (size_t)((t + 1) * PH_KV + wn * 32) * Ddim;
        const float* vgn = vbase + (size_t)((t + 1) * PH_KV + wn * 32) * Ddim;

        // stage K wave 0 (next phase)
        float4 kf[4];
        if (more) {
            #pragma unroll
            for (int i = 0; i < 4; i++)
                kf[i] = *reinterpret_cast<const float4*>(kgn + kr * Ddim + 16 * i + 4 * kq);
        }

        // ---- GEMM1: S(m16 x kv32) over d=128 (8 k16 steps x 4 nb) ----
        float S[4][4];
        #pragma unroll
        for (int nb = 0; nb < 4; nb++)
            #pragma unroll
            for (int i = 0; i < 4; i++) S[nb][i] = 0.0f;

        const uint32_t* kw0 = Kb + g * KWSTRIDE + t4;
        #pragma unroll
        for (int kb = 0; kb < 8; kb++) {
            uint32_t a0 = qw0[8 * kb];
            uint32_t a1 = qw0[8 * QWSTRIDE + 8 * kb];
            uint32_t a2 = qw0[8 * kb + 4];
            uint32_t a3 = qw0[8 * QWSTRIDE + 8 * kb + 4];
            #pragma unroll
            for (int nb = 0; nb < 4; nb++) {
                const uint32_t* kp = kw0 + nb * 8 * KWSTRIDE + 8 * kb;
                mma16(S[nb], a0, a1, a2, a3, kp[0], kp[4]);
            }
        }

        // store staged K wave 0, stage+store K wave 1
        if (more) {
            #pragma unroll
            for (int i = 0; i < 4; i++)
                *reinterpret_cast<uint2*>(kd + kr * KWSTRIDE + 8 * i + 2 * kq) =
                    make_uint2(h2(kf[i].x, kf[i].y), h2(kf[i].z, kf[i].w));
            #pragma unroll
            for (int i = 4; i < 8; i++) {
                float4 f = *reinterpret_cast<const float4*>(kgn + kr * Ddim + 16 * i + 4 * kq);
                *reinterpret_cast<uint2*>(kd + kr * KWSTRIDE + 8 * i + 2 * kq) =
                    make_uint2(h2(f.x, f.y), h2(f.z, f.w));
            }
        }

        // ---- P = f16(relu(S)^2) packed (C->A direct) ----
        uint32_t pA[2][4];
        #pragma unroll
        for (int s2 = 0; s2 < 2; s2++) {
            float p00 = fmaxf(S[2 * s2][0], 0.0f),     p01 = fmaxf(S[2 * s2][1], 0.0f);
            float p02 = fmaxf(S[2 * s2][2], 0.0f),     p03 = fmaxf(S[2 * s2][3], 0.0f);
            float p10 = fmaxf(S[2 * s2 + 1][0], 0.0f), p11 = fmaxf(S[2 * s2 + 1][1], 0.0f);
            float p12 = fmaxf(S[2 * s2 + 1][2], 0.0f), p13 = fmaxf(S[2 * s2 + 1][3], 0.0f);
            pA[s2][0] = h2(p00 * p00, p01 * p01);
            pA[s2][1] = h2(p02 * p02, p03 * p03);
            pA[s2][2] = h2(p10 * p10, p11 * p11);
            pA[s2][3] = h2(p12 * p12, p13 * p13);
        }

        // stage V (next phase)
        float4 va[4], vb2[4];
        if (more) {
            #pragma unroll
            for (int m = 0; m < 4; m++) {
                int d0 = 4 * vc + 32 * m;
                va[m]  = *reinterpret_cast<const float4*>(vgn + (2 * vrp) * Ddim + d0);
                vb2[m] = *reinterpret_cast<const float4*>(vgn + (2 * vrp + 1) * Ddim + d0);
            }
        }

        // ---- GEMM2: O += P @ V'' (2 k16 steps x 16 nd) ----
        #pragma unroll
        for (int s2 = 0; s2 < 2; s2++) {
            const uint32_t* v0 = Vb + (8 * s2 + t4) * VWSTRIDE + g;
            const uint32_t* v1 = v0 + 4 * VWSTRIDE;
            #pragma unroll
            for (int nd = 0; nd < 16; nd++)
                mma16(O[nd], pA[s2][0], pA[s2][1], pA[s2][2], pA[s2][3],
                      v0[8 * nd], v1[8 * nd]);
        }

        // store staged V
        if (more) {
            #pragma unroll
            for (int m = 0; m < 4; m++) {
                int d0 = 4 * vc + 32 * m;
                *reinterpret_cast<uint4*>(vd + vrp * VWSTRIDE + d0) =
                    make_uint4(h2(va[m].x, vb2[m].x), h2(va[m].y, vb2[m].y),
                               h2(va[m].z, vb2[m].z), h2(va[m].w, vb2[m].w));
            }
        }

        bar_sync(1 + wn, 128);
    }

    // ---- reduce O across the two kv groups, write out ----
    __syncthreads();
    float* red = reinterpret_cast<float*>(KW);   // 64 x 136 floats
    if (wn == 1) {
        int r0 = wm * 16 + g;
        #pragma unroll
        for (int nd = 0; nd < 16; nd++) {
            *reinterpret_cast<float2*>(red + r0 * 136 + nd * 8 + 2 * t4) =
                make_float2(O[nd][0], O[nd][1]);
            *reinterpret_cast<float2*>(red + (r0 + 8) * 136 + nd * 8 + 2 * t4) =
                make_float2(O[nd][2], O[nd][3]);
        }
    }
    __syncthreads();
    if (wn == 0) {
        float* ob = out + ((size_t)bh * Sdim + q0) * Ddim;
        int r0 = wm * 16 + g;
        #pragma unroll
        for (int nd = 0; nd < 16; nd++) {
            float2 ra = *reinterpret_cast<const float2*>(red + r0 * 136 + nd * 8 + 2 * t4);
            float2 rb = *reinterpret_cast<const float2*>(red + (r0 + 8) * 136 + nd * 8 + 2 * t4);
            *reinterpret_cast<float2*>(ob + r0 * Ddim + nd * 8 + 2 * t4) =
                make_float2(O[nd][0] + ra.x, O[nd][1] + ra.y);
            *reinterpret_cast<float2*>(ob + (r0 + 8) * Ddim + nd * 8 + 2 * t4) =
                make_float2(O[nd][2] + rb.x, O[nd][3] + rb.y);
        }
    }
}

extern "C" void kernel_launch(void* const* d_in, const int* in_sizes, int n_in,
                              void* d_out, int out_size) {
    (void)in_sizes; (void)n_in; (void)out_size;
    const float* q = (const float*)d_in[0];
    const float* k = (const float*)d_in[1];
    const float* v = (const float*)d_in[2];
    const float* scale = (const float*)d_in[3];
    float* out = (float*)d_out;

    cudaFuncSetAttribute(attn_relu2_kernel,
                         cudaFuncAttributeMaxDynamicSharedMemorySize, SMEM_BYTES);

    dim3 grid(Bdim * Hdim * (Sdim / QT));   // 1024 CTAs, bh-major
    attn_relu2_kernel<<<grid, NTHREADS, SMEM_BYTES>>>(q, k, v, scale, out);
}

// round 8
// speedup vs baseline: 5.4086x; 1.6104x over previous
#include <cuda_runtime.h>
#include <cstdint>

#define Bdim 2
#define Hdim 16
#define Sdim 2048
#define Ddim 128
#define QT 128           // q-tile rows per CTA
#define PH_KV 64         // kv rows consumed per phase (32 per group)
#define NPH (Sdim / PH_KV)   // 32 phases
#define NTHREADS 256

// word strides (fp16 packed as uint32 words)
#define QWSTRIDE 72      // Q row: 64 words + 8 pad (LDS.64-conflict-free)
#define KWSTRIDE 72      // K row: 64 words + 8 pad
#define VWSTRIDE 136     // V'' rpair row: 128 words + 8 pad

#define QS_OFF 0
#define KS_OFF (QT * QWSTRIDE)                    // 9216
#define VS_OFF (KS_OFF + 4 * 32 * KWSTRIDE)       // K: 2grp x 2buf x 32 rows
#define SMEM_WORDS (VS_OFF + 4 * 16 * VWSTRIDE)   // V'': 2grp x 2buf x 16 rpairs
#define SMEM_BYTES (SMEM_WORDS * 4)               // 108544 B -> 1 CTA/SM

// ---------------------------------------------------------------------------
// pack two f32 into f16x2 word: lo -> low half, hi -> high half.
static __device__ __forceinline__ uint32_t h2(float lo, float hi) {
    uint32_t r;
    asm("cvt.rn.f16x2.f32 %0, %1, %2;" : "=r"(r) : "f"(hi), "f"(lo));
    return r;
}

static __device__ __forceinline__ void mma16(float* d,
        uint32_t a0, uint32_t a1, uint32_t a2, uint32_t a3,
        uint32_t b0, uint32_t b1) {
    asm volatile(
        "mma.sync.aligned.m16n8k16.row.col.f32.f16.f16.f32 "
        "{%0,%1,%2,%3}, {%4,%5,%6,%7}, {%8,%9}, {%0,%1,%2,%3};"
        : "+f"(d[0]), "+f"(d[1]), "+f"(d[2]), "+f"(d[3])
        : "r"(a0), "r"(a1), "r"(a2), "r"(a3), "r"(b0), "r"(b1));
}

static __device__ __forceinline__ void bar_sync(int id, int cnt) {
    asm volatile("bar.sync %0, %1;" :: "r"(id), "r"(cnt) : "memory");
}

// ---------------------------------------------------------------------------
// One CTA (256 thr, 8 warps) = one (b,h) x one 128-row q-tile. 1 CTA/SM.
// wm = wid&3 (m32 block), wn = wid>>2 (kv group, 32 rows/phase each).
// k-order permutation (d = 16kb + {4t4..4t4+3} for k-pos {2t4,2t4+1,2t4+8,2t4+9})
// makes Q/K fragments single LDS.64 from natural row-major fp16 smem.
// GEMM1 S(m32 x kv32); P = f16(relu(S)^2) in regs (C->A direct);
// GEMM2 O(m32 x d128) += P @ V'' (row-pair packed, frag reused by 2 mma).
// K/V double-buffered per group via LDG->cvt->STS staging; 1 named bar/phase.
// O reduced across the two groups at the end.
// ---------------------------------------------------------------------------
__global__ void __launch_bounds__(NTHREADS, 1)
attn_relu2_kernel(const float* __restrict__ q, const float* __restrict__ k,
                  const float* __restrict__ v, const float* __restrict__ scale_p,
                  float* __restrict__ out) {
    extern __shared__ uint32_t smw[];
    uint32_t* QW = smw + QS_OFF;
    uint32_t* KW = smw + KS_OFF;
    uint32_t* VW = smw + VS_OFF;

    const int tid  = threadIdx.x;
    const int lane = tid & 31;
    const int g    = lane >> 2;    // 0..7
    const int t4   = lane & 3;     // 0..3
    const int wid  = tid >> 5;
    const int wm   = wid & 3;      // m32 block
    const int wn   = wid >> 2;     // kv group
    const int tid_h = tid & 127;

    const int bh = blockIdx.x >> 4;           // 0..31
    const int q0 = (blockIdx.x & 15) << 7;    // q-tile base (128 rows)

    const float* kbase = k + (size_t)bh * Sdim * Ddim;
    const float* vbase = v + (size_t)bh * Sdim * Ddim;

    // load coords: K linear full-row; V row-pair packer
    const int kcol = tid_h & 31;       // float4 column (floats 4*kcol)
    const int krow0 = tid_h >> 5;      // rows krow0 + 4i
    const int vrp = tid_h >> 3, vc = tid_h & 7;

    // ---- Q fill (scale folded, fp16 packed, natural row-major) ----
    {
        const float scl = *scale_p;
        const float* qg = q + ((size_t)bh * Sdim + q0) * Ddim;
        #pragma unroll
        for (int i = 0; i < 16; i++) {
            int c = tid + NTHREADS * i;       // 0..4095
            int r = c >> 5, j = c & 31;
            float4 f = *reinterpret_cast<const float4*>(qg + r * Ddim + 4 * j);
            *reinterpret_cast<uint2*>(QW + r * QWSTRIDE + 2 * j) =
                make_uint2(h2(f.x * scl, f.y * scl), h2(f.z * scl, f.w * scl));
        }
    }

    // ---- prologue: phase-0 K/V into buf 0 ----
    {
        const float* kg = kbase + (size_t)(wn * 32) * Ddim;
        uint32_t* kd = KW + (wn * 2 + 0) * 32 * KWSTRIDE;
        #pragma unroll
        for (int i = 0; i < 8; i++) {
            int r = krow0 + 4 * i;
            float4 f = *reinterpret_cast<const float4*>(kg + r * Ddim + 4 * kcol);
            *reinterpret_cast<uint2*>(kd + r * KWSTRIDE + 2 * kcol) =
                make_uint2(h2(f.x, f.y), h2(f.z, f.w));
        }
        const float* vg = vbase + (size_t)(wn * 32) * Ddim;
        uint32_t* vd = VW + (wn * 2 + 0) * 16 * VWSTRIDE;
        #pragma unroll
        for (int m = 0; m < 4; m++) {
            int d0 = 4 * vc + 32 * m;
            float4 a = *reinterpret_cast<const float4*>(vg + (2 * vrp) * Ddim + d0);
            float4 b = *reinterpret_cast<const float4*>(vg + (2 * vrp + 1) * Ddim + d0);
            *reinterpret_cast<uint4*>(vd + vrp * VWSTRIDE + d0) =
                make_uint4(h2(a.x, b.x), h2(a.y, b.y), h2(a.z, b.z), h2(a.w, b.w));
        }
    }
    __syncthreads();

    float O[2][16][4];
    #pragma unroll
    for (int mb = 0; mb < 2; mb++)
        #pragma unroll
        for (int nd = 0; nd < 16; nd++)
            #pragma unroll
            for (int i = 0; i < 4; i++) O[mb][nd][i] = 0.0f;

    const uint32_t* qA = QW + (wm * 32 + g) * QWSTRIDE + 2 * t4;

    // ---- main loop: 32 phases ----
    #pragma unroll 1
    for (int t = 0; t < NPH; t++) {
        const int buf = t & 1;
        const bool more = (t + 1 < NPH);
        const uint32_t* Kb = KW + (wn * 2 + buf) * 32 * KWSTRIDE;
        const uint32_t* Vb = VW + (wn * 2 + buf) * 16 * VWSTRIDE;
        uint32_t* kd = KW + (wn * 2 + (buf ^ 1)) * 32 * KWSTRIDE;
        uint32_t* vd = VW + (wn * 2 + (buf ^ 1)) * 16 * VWSTRIDE;
        const float* kgn = kbase + (size_t)((t + 1) * PH_KV + wn * 32) * Ddim;
        const float* vgn = vbase + (size_t)((t + 1) * PH_KV + wn * 32) * Ddim;

        // stage next K (LDG overlaps GEMM1)
        float4 kf[8];
        if (more) {
            #pragma unroll
            for (int i = 0; i < 8; i++)
                kf[i] = *reinterpret_cast<const float4*>(kgn + (krow0 + 4 * i) * Ddim + 4 * kcol);
        }

        // ---- GEMM1: S(m32 x kv32), 8 k16-steps, LDS.64 frags ----
        float S[2][4][4];
        #pragma unroll
        for (int mb = 0; mb < 2; mb++)
            #pragma unroll
            for (int nb = 0; nb < 4; nb++)
                #pragma unroll
                for (int i = 0; i < 4; i++) S[mb][nb][i] = 0.0f;

        const uint32_t* kB0 = Kb + g * KWSTRIDE + 2 * t4;
        #pragma unroll
        for (int kb = 0; kb < 8; kb++) {
            uint2 A00 = *reinterpret_cast<const uint2*>(qA + 8 * kb);
            uint2 A01 = *reinterpret_cast<const uint2*>(qA + 8 * QWSTRIDE + 8 * kb);
            uint2 A10 = *reinterpret_cast<const uint2*>(qA + 16 * QWSTRIDE + 8 * kb);
            uint2 A11 = *reinterpret_cast<const uint2*>(qA + 24 * QWSTRIDE + 8 * kb);
            #pragma unroll
            for (int nb = 0; nb < 4; nb++) {
                uint2 B = *reinterpret_cast<const uint2*>(kB0 + nb * 8 * KWSTRIDE + 8 * kb);
                mma16(S[0][nb], A00.x, A01.x, A00.y, A01.y, B.x, B.y);
                mma16(S[1][nb], A10.x, A11.x, A10.y, A11.y, B.x, B.y);
            }
        }

        // store staged K; stage next V
        if (more) {
            #pragma unroll
            for (int i = 0; i < 8; i++)
                *reinterpret_cast<uint2*>(kd + (krow0 + 4 * i) * KWSTRIDE + 2 * kcol) =
                    make_uint2(h2(kf[i].x, kf[i].y), h2(kf[i].z, kf[i].w));
        }
        float4 va[4], vb2[4];
        if (more) {
            #pragma unroll
            for (int m = 0; m < 4; m++) {
                int d0 = 4 * vc + 32 * m;
                va[m]  = *reinterpret_cast<const float4*>(vgn + (2 * vrp) * Ddim + d0);
                vb2[m] = *reinterpret_cast<const float4*>(vgn + (2 * vrp + 1) * Ddim + d0);
            }
        }

        // ---- P = f16(relu(S)^2); GEMM2: O += P @ V'' (frag serves 2 mma) ----
        #pragma unroll
        for (int s2 = 0; s2 < 2; s2++) {
            uint32_t pA[2][4];
            #pragma unroll
            for (int mb = 0; mb < 2; mb++) {
                float p00 = fmaxf(S[mb][2 * s2][0], 0.0f),     p01 = fmaxf(S[mb][2 * s2][1], 0.0f);
                float p02 = fmaxf(S[mb][2 * s2][2], 0.0f),     p03 = fmaxf(S[mb][2 * s2][3], 0.0f);
                float p10 = fmaxf(S[mb][2 * s2 + 1][0], 0.0f), p11 = fmaxf(S[mb][2 * s2 + 1][1], 0.0f);
                float p12 = fmaxf(S[mb][2 * s2 + 1][2], 0.0f), p13 = fmaxf(S[mb][2 * s2 + 1][3], 0.0f);
                pA[mb][0] = h2(p00 * p00, p01 * p01);
                pA[mb][1] = h2(p02 * p02, p03 * p03);
                pA[mb][2] = h2(p10 * p10, p11 * p11);
                pA[mb][3] = h2(p12 * p12, p13 * p13);
            }
            const uint32_t* v0 = Vb + (8 * s2 + t4) * VWSTRIDE + g;
            const uint32_t* v1 = v0 + 4 * VWSTRIDE;
            #pragma unroll
            for (int nd = 0; nd < 16; nd++) {
                uint32_t b0 = v0[8 * nd], b1 = v1[8 * nd];
                mma16(O[0][nd], pA[0][0], pA[0][1], pA[0][2], pA[0][3], b0, b1);
                mma16(O[1][nd], pA[1][0], pA[1][1], pA[1][2], pA[1][3], b0, b1);
            }
        }

        // store staged V
        if (more) {
            #pragma unroll
            for (int m = 0; m < 4; m++) {
                int d0 = 4 * vc + 32 * m;
                *reinterpret_cast<uint4*>(vd + vrp * VWSTRIDE + d0) =
                    make_uint4(h2(va[m].x, vb2[m].x), h2(va[m].y, vb2[m].y),
                               h2(va[m].z, vb2[m].z), h2(va[m].w, vb2[m].w));
            }
        }

        bar_sync(1 + wn, 128);
    }

    // ---- reduce O across the two kv groups, write out ----
    __syncthreads();
    float* red = reinterpret_cast<float*>(smw);   // 128 x 132 floats
    if (wn == 1) {
        #pragma unroll
        for (int mb = 0; mb < 2; mb++) {
            int r0 = wm * 32 + mb * 16 + g;
            #pragma unroll
            for (int nd = 0; nd < 16; nd++) {
                *reinterpret_cast<float2*>(red + r0 * 132 + nd * 8 + 2 * t4) =
                    make_float2(O[mb][nd][0], O[mb][nd][1]);
                *reinterpret_cast<float2*>(red + (r0 + 8) * 132 + nd * 8 + 2 * t4) =
                    make_float2(O[mb][nd][2], O[mb][nd][3]);
            }
        }
    }
    __syncthreads();
    if (wn == 0) {
        float* ob = out + ((size_t)bh * Sdim + q0) * Ddim;
        #pragma unroll
        for (int mb = 0; mb < 2; mb++) {
            int r0 = wm * 32 + mb * 16 + g;
            #pragma unroll
            for (int nd = 0; nd < 16; nd++) {
                float2 ra = *reinterpret_cast<const float2*>(red + r0 * 132 + nd * 8 + 2 * t4);
                float2 rb = *reinterpret_cast<const float2*>(red + (r0 + 8) * 132 + nd * 8 + 2 * t4);
                *reinterpret_cast<float2*>(ob + r0 * Ddim + nd * 8 + 2 * t4) =
                    make_float2(O[mb][nd][0] + ra.x, O[mb][nd][1] + ra.y);
                *reinterpret_cast<float2*>(ob + (r0 + 8) * Ddim + nd * 8 + 2 * t4) =
                    make_float2(O[mb][nd][2] + rb.x, O[mb][nd][3] + rb.y);
            }
        }
    }
}

extern "C" void kernel_launch(void* const* d_in, const int* in_sizes, int n_in,
                              void* d_out, int out_size) {
    (void)in_sizes; (void)n_in; (void)out_size;
    const float* q = (const float*)d_in[0];
    const float* k = (const float*)d_in[1];
    const float* v = (const float*)d_in[2];
    const float* scale = (const float*)d_in[3];
    float* out = (float*)d_out;

    cudaFuncSetAttribute(attn_relu2_kernel,
                         cudaFuncAttributeMaxDynamicSharedMemorySize, SMEM_BYTES);

    dim3 grid(Bdim * Hdim * (Sdim / QT));   // 512 CTAs, bh-major
    attn_relu2_kernel<<<grid, NTHREADS, SMEM_BYTES>>>(q, k, v, scale, out);
}

// round 9
// speedup vs baseline: 7.1561x; 1.3231x over previous
#include <cuda_runtime.h>
#include <cstdint>

#define Bdim 2
#define Hdim 16
#define Sdim 2048
#define Ddim 128
#define QT 128            // q-tile rows per CTA
#define PH_KV 64          // kv rows per phase (32 per group)
#define NPH (Sdim / PH_KV)   // 32 phases
#define NTHREADS 256
#define WST 68            // fp16 tile word stride (ldmatrix conflict-free)

// smem word offsets
#define QS_OFF  0
#define K16_OFF (QT * WST)                    // 8704
#define V16_OFF (K16_OFF + 4 * 32 * WST)      // K16: 2grp x 2buf x 32 rows
#define KF_OFF  (V16_OFF + 4 * 32 * WST)      // V16: same
#define VF_OFF  (KF_OFF + 2 * 32 * 128)       // fp32 staging: 2grp x 32 x 128
#define SMEM_WORDS (VF_OFF + 2 * 32 * 128)
#define SMEM_BYTES (SMEM_WORDS * 4)           // 169984 B -> 1 CTA/SM

// ---------------------------------------------------------------------------
static __device__ __forceinline__ uint32_t h2(float lo, float hi) {
    uint32_t r;
    asm("cvt.rn.f16x2.f32 %0, %1, %2;" : "=r"(r) : "f"(hi), "f"(lo));
    return r;
}
// relu^2 in f16x2: max(w,0) then square
static __device__ __forceinline__ uint32_t hsq(uint32_t w) {
    uint32_t r;
    asm("max.f16x2 %0, %1, %2;" : "=r"(r) : "r"(w), "r"(0u));
    asm("mul.f16x2 %0, %1, %1;" : "=r"(r) : "r"(r));
    return r;
}

static __device__ __forceinline__ void mma16(float* d,
        uint32_t a0, uint32_t a1, uint32_t a2, uint32_t a3,
        uint32_t b0, uint32_t b1) {
    asm volatile(
        "mma.sync.aligned.m16n8k16.row.col.f32.f16.f16.f32 "
        "{%0,%1,%2,%3}, {%4,%5,%6,%7}, {%8,%9}, {%0,%1,%2,%3};"
        : "+f"(d[0]), "+f"(d[1]), "+f"(d[2]), "+f"(d[3])
        : "r"(a0), "r"(a1), "r"(a2), "r"(a3), "r"(b0), "r"(b1));
}

static __device__ __forceinline__ void ldm4(uint32_t addr, uint32_t* r) {
    asm volatile("ldmatrix.sync.aligned.m8n8.x4.shared.b16 {%0,%1,%2,%3}, [%4];"
        : "=r"(r[0]), "=r"(r[1]), "=r"(r[2]), "=r"(r[3]) : "r"(addr));
}
static __device__ __forceinline__ void ldm4t(uint32_t addr, uint32_t* r) {
    asm volatile("ldmatrix.sync.aligned.m8n8.x4.trans.shared.b16 {%0,%1,%2,%3}, [%4];"
        : "=r"(r[0]), "=r"(r[1]), "=r"(r[2]), "=r"(r[3]) : "r"(addr));
}

static __device__ __forceinline__ void cp16(const float* smem_dst, const float* gsrc) {
    unsigned sa = (unsigned)__cvta_generic_to_shared(smem_dst);
    asm volatile("cp.async.cg.shared.global [%0], [%1], 16;" :: "r"(sa), "l"(gsrc));
}
#define CP_COMMIT() asm volatile("cp.async.commit_group;" ::: "memory")
#define CP_WAIT0()  asm volatile("cp.async.wait_group 0;" ::: "memory")

static __device__ __forceinline__ void bar_sync(int id, int cnt) {
    asm volatile("bar.sync %0, %1;" :: "r"(id), "r"(cnt) : "memory");
}

// ---------------------------------------------------------------------------
// One CTA (256 thr, 8 warps) = one (b,h) x one 128-row q-tile. 1 CTA/SM.
// wm = wid&3 (m32 block), wn = wid>>2 (kv group, 32 rows/phase).
// Per phase: issue cp.async (fp32 K/V, tile t+1) -> GEMM1 (ldmatrix frags)
// -> P = relu^2 in f16x2 (C->A direct) -> GEMM2 (ldmatrix.trans V) ->
// cp.wait + fp32->fp16 smem convert into spare fp16 buffer. One named bar
// per phase per group. O reduced across the two groups at the end.
// ---------------------------------------------------------------------------
__global__ void __launch_bounds__(NTHREADS, 1)
attn_relu2_kernel(const float* __restrict__ q, const float* __restrict__ k,
                  const float* __restrict__ v, const float* __restrict__ scale_p,
                  float* __restrict__ out) {
    extern __shared__ uint32_t smw[];
    uint32_t* QW = smw + QS_OFF;
    float* KF = reinterpret_cast<float*>(smw + KF_OFF);
    float* VF = reinterpret_cast<float*>(smw + VF_OFF);

    const int tid  = threadIdx.x;
    const int lane = tid & 31;
    const int g    = lane >> 2;
    const int t4   = lane & 3;
    const int wid  = tid >> 5;
    const int wm   = wid & 3;      // m32 block
    const int wn   = wid >> 2;     // kv group
    const int tid_h = tid & 127;

    const int bh = blockIdx.x >> 4;
    const int q0 = (blockIdx.x & 15) << 7;

    const float* kbase = k + (size_t)bh * Sdim * Ddim;
    const float* vbase = v + (size_t)bh * Sdim * Ddim;

    // ldmatrix lane geometry (shared by A, B, V tiles)
    const int rl8 = (((lane >> 3) & 1) << 3) + (lane & 7);  // row within 16
    const int c4  = ((lane >> 4) & 1) << 2;                 // 0 or 4 words

    const uint32_t sb = (uint32_t)__cvta_generic_to_shared(smw);
    const uint32_t qa0 = sb + 4 * (QS_OFF + (wm * 32 + rl8) * WST + c4);
    const uint32_t qa1 = qa0 + 4 * 16 * WST;

    // group staging bases
    float* kf = KF + wn * 32 * 128;
    float* vf = VF + wn * 32 * 128;

    // ---- Q fill (scale folded, fp16, natural row-major) ----
    {
        const float scl = *scale_p;
        const float* qg = q + ((size_t)bh * Sdim + q0) * Ddim;
        #pragma unroll
        for (int i = 0; i < 16; i++) {
            int c = tid + NTHREADS * i;       // 0..4095
            int r = c >> 5, j = c & 31;
            float4 f = *reinterpret_cast<const float4*>(qg + r * Ddim + 4 * j);
            *reinterpret_cast<uint2*>(QW + r * WST + 2 * j) =
                make_uint2(h2(f.x * scl, f.y * scl), h2(f.z * scl, f.w * scl));
        }
    }

    // ---- prologue: cp.async tile 0 -> wait -> convert into fp16 buf 0 ----
    {
        const float* kg = kbase + (size_t)(wn * 32) * Ddim;
        const float* vg = vbase + (size_t)(wn * 32) * Ddim;
        #pragma unroll
        for (int i = 0; i < 8; i++) {
            int c = tid_h + 128 * i;          // 0..1023
            int r = c >> 5, j = c & 31;
            cp16(kf + r * 128 + 4 * j, kg + r * Ddim + 4 * j);
        }
        #pragma unroll
        for (int i = 0; i < 8; i++) {
            int c = tid_h + 128 * i;
            int r = c >> 5, j = c & 31;
            cp16(vf + r * 128 + 4 * j, vg + r * Ddim + 4 * j);
        }
        CP_COMMIT();
        CP_WAIT0();
        uint32_t* kd = smw + K16_OFF + (wn * 2 + 0) * 32 * WST;
        uint32_t* vd = smw + V16_OFF + (wn * 2 + 0) * 32 * WST;
        #pragma unroll
        for (int i = 0; i < 8; i++) {
            int c = tid_h + 128 * i;
            int r = c >> 5, j = c & 31;
            float4 f = *reinterpret_cast<const float4*>(kf + r * 128 + 4 * j);
            *reinterpret_cast<uint2*>(kd + r * WST + 2 * j) =
                make_uint2(h2(f.x, f.y), h2(f.z, f.w));
            float4 e = *reinterpret_cast<const float4*>(vf + r * 128 + 4 * j);
            *reinterpret_cast<uint2*>(vd + r * WST + 2 * j) =
                make_uint2(h2(e.x, e.y), h2(e.z, e.w));
        }
    }
    __syncthreads();

    float O[2][16][4];
    #pragma unroll
    for (int mb = 0; mb < 2; mb++)
        #pragma unroll
        for (int nd = 0; nd < 16; nd++)
            #pragma unroll
            for (int i = 0; i < 4; i++) O[mb][nd][i] = 0.0f;

    // ---- main loop: 32 phases ----
    #pragma unroll 1
    for (int t = 0; t < NPH; t++) {
        const int buf = t & 1;
        const bool more = (t + 1 < NPH);

        bar_sync(1 + wn, 128);   // fp16[buf] ready; staging reads done

        // issue cp.async for tile t+1 (overlaps this phase's compute)
        if (more) {
            const float* kgn = kbase + (size_t)((t + 1) * PH_KV + wn * 32) * Ddim;
            const float* vgn = vbase + (size_t)((t + 1) * PH_KV + wn * 32) * Ddim;
            #pragma unroll
            for (int i = 0; i < 8; i++) {
                int c = tid_h + 128 * i;
                int r = c >> 5, j = c & 31;
                cp16(kf + r * 128 + 4 * j, kgn + r * Ddim + 4 * j);
            }
            #pragma unroll
            for (int i = 0; i < 8; i++) {
                int c = tid_h + 128 * i;
                int r = c >> 5, j = c & 31;
                cp16(vf + r * 128 + 4 * j, vgn + r * Ddim + 4 * j);
            }
            CP_COMMIT();
        }

        const uint32_t kb_b = sb + 4 * (K16_OFF + (wn * 2 + buf) * 32 * WST
                                        + rl8 * WST + c4);
        const uint32_t vb_b = sb + 4 * (V16_OFF + (wn * 2 + buf) * 32 * WST
                                        + rl8 * WST + c4);

        // ---- GEMM1: S(m32 x kv32), 8 k16-steps, ldmatrix fragments ----
        float S[2][4][4];
        #pragma unroll
        for (int mb = 0; mb < 2; mb++)
            #pragma unroll
            for (int nb = 0; nb < 4; nb++)
                #pragma unroll
                for (int i = 0; i < 4; i++) S[mb][nb][i] = 0.0f;

        #pragma unroll
        for (int kb = 0; kb < 8; kb++) {
            uint32_t A0[4], A1[4], B0[4], B1[4];
            ldm4(qa0 + 32 * kb, A0);                      // m 0-15
            ldm4(qa1 + 32 * kb, A1);                      // m 16-31
            ldm4(kb_b + 32 * kb, B0);                     // kv 0-15
            ldm4(kb_b + 4 * 16 * WST + 32 * kb, B1);      // kv 16-31
            mma16(S[0][0], A0[0], A0[1], A0[2], A0[3], B0[0], B0[2]);
            mma16(S[0][1], A0[0], A0[1], A0[2], A0[3], B0[1], B0[3]);
            mma16(S[0][2], A0[0], A0[1], A0[2], A0[3], B1[0], B1[2]);
            mma16(S[0][3], A0[0], A0[1], A0[2], A0[3], B1[1], B1[3]);
            mma16(S[1][0], A1[0], A1[1], A1[2], A1[3], B0[0], B0[2]);
            mma16(S[1][1], A1[0], A1[1], A1[2], A1[3], B0[1], B0[3]);
            mma16(S[1][2], A1[0], A1[1], A1[2], A1[3], B1[0], B1[2]);
            mma16(S[1][3], A1[0], A1[1], A1[2], A1[3], B1[1], B1[3]);
        }

        // ---- P = relu(S)^2 (f16x2); GEMM2: O += P @ V (ldmatrix.trans) ----
        #pragma unroll
        for (int s2 = 0; s2 < 2; s2++) {
            uint32_t pA[2][4];
            #pragma unroll
            for (int mb = 0; mb < 2; mb++) {
                pA[mb][0] = hsq(h2(S[mb][2 * s2][0],     S[mb][2 * s2][1]));
                pA[mb][1] = hsq(h2(S[mb][2 * s2][2],     S[mb][2 * s2][3]));
                pA[mb][2] = hsq(h2(S[mb][2 * s2 + 1][0], S[mb][2 * s2 + 1][1]));
                pA[mb][3] = hsq(h2(S[mb][2 * s2 + 1][2], S[mb][2 * s2 + 1][3]));
            }
            const uint32_t va_b = vb_b + 4 * 16 * WST * s2;
            #pragma unroll
            for (int j = 0; j < 8; j++) {
                uint32_t Vr[4];
                ldm4t(va_b + 32 * j, Vr);    // b0/b1 for nd=2j, 2j+1
                mma16(O[0][2 * j],     pA[0][0], pA[0][1], pA[0][2], pA[0][3], Vr[0], Vr[1]);
                mma16(O[0][2 * j + 1], pA[0][0], pA[0][1], pA[0][2], pA[0][3], Vr[2], Vr[3]);
                mma16(O[1][2 * j],     pA[1][0], pA[1][1], pA[1][2], pA[1][3], Vr[0], Vr[1]);
                mma16(O[1][2 * j + 1], pA[1][0], pA[1][1], pA[1][2], pA[1][3], Vr[2], Vr[3]);
            }
        }

        // ---- wait + convert tile t+1 into spare fp16 buffer ----
        if (more) {
            CP_WAIT0();
            uint32_t* kd = smw + K16_OFF + (wn * 2 + (buf ^ 1)) * 32 * WST;
            uint32_t* vd = smw + V16_OFF + (wn * 2 + (buf ^ 1)) * 32 * WST;
            #pragma unroll
            for (int i = 0; i < 8; i++) {
                int c = tid_h + 128 * i;
                int r = c >> 5, j = c & 31;
                float4 f = *reinterpret_cast<const float4*>(kf + r * 128 + 4 * j);
                *reinterpret_cast<uint2*>(kd + r * WST + 2 * j) =
                    make_uint2(h2(f.x, f.y), h2(f.z, f.w));
                float4 e = *reinterpret_cast<const float4*>(vf + r * 128 + 4 * j);
                *reinterpret_cast<uint2*>(vd + r * WST + 2 * j) =
                    make_uint2(h2(e.x, e.y), h2(e.z, e.w));
            }
        }
    }

    // ---- reduce O across the two kv groups, write out ----
    __syncthreads();
    float* red = reinterpret_cast<float*>(smw);   // 128 x 132 floats
    if (wn == 1) {
        #pragma unroll
        for (int mb = 0; mb < 2; mb++) {
            int r0 = wm * 32 + mb * 16 + g;
            #pragma unroll
            for (int nd = 0; nd < 16; nd++) {
                *reinterpret_cast<float2*>(red + r0 * 132 + nd * 8 + 2 * t4) =
                    make_float2(O[mb][nd][0], O[mb][nd][1]);
                *reinterpret_cast<float2*>(red + (r0 + 8) * 132 + nd * 8 + 2 * t4) =
                    make_float2(O[mb][nd][2], O[mb][nd][3]);
            }
        }
    }
    __syncthreads();
    if (wn == 0) {
        float* ob = out + ((size_t)bh * Sdim + q0) * Ddim;
        #pragma unroll
        for (int mb = 0; mb < 2; mb++) {
            int r0 = wm * 32 + mb * 16 + g;
            #pragma unroll
            for (int nd = 0; nd < 16; nd++) {
                float2 ra = *reinterpret_cast<const float2*>(red + r0 * 132 + nd * 8 + 2 * t4);
                float2 rb = *reinterpret_cast<const float2*>(red + (r0 + 8) * 132 + nd * 8 + 2 * t4);
                *reinterpret_cast<float2*>(ob + r0 * Ddim + nd * 8 + 2 * t4) =
                    make_float2(O[mb][nd][0] + ra.x, O[mb][nd][1] + ra.y);
                *reinterpret_cast<float2*>(ob + (r0 + 8) * Ddim + nd * 8 + 2 * t4) =
                    make_float2(O[mb][nd][2] + rb.x, O[mb][nd][3] + rb.y);
            }
        }
    }
}

extern "C" void kernel_launch(void* const* d_in, const int* in_sizes, int n_in,
                              void* d_out, int out_size) {
    (void)in_sizes; (void)n_in; (void)out_size;
    const float* q = (const float*)d_in[0];
    const float* k = (const float*)d_in[1];
    const float* v = (const float*)d_in[2];
    const float* scale = (const float*)d_in[3];
    float* out = (float*)d_out;

    cudaFuncSetAttribute(attn_relu2_kernel,
                         cudaFuncAttributeMaxDynamicSharedMemorySize, SMEM_BYTES);

    dim3 grid(Bdim * Hdim * (Sdim / QT));   // 512 CTAs, bh-major
    attn_relu2_kernel<<<grid, NTHREADS, SMEM_BYTES>>>(q, k, v, scale, out);
}